// round 8
// baseline (speedup 1.0000x reference)
#include <cuda_runtime.h>
#include <cstdint>

#define DD 128
#define MAXM 200000
#define MAXR 256
#define MAXB 8

// -------- scratch (static device memory; no allocs allowed) --------
__device__ float g_Hs[(size_t)MAXM * DD];   // hidden @ Ws^T      (102.4 MB)
__device__ float g_agg[(size_t)MAXM * DD];  // segment_sum output (102.4 MB)
__device__ int   g_deg[MAXM];
__device__ float g_Rr[MAXR * DD];           // rela_embed @ Wr^T
__device__ float g_Qq[MAXB * DD];           // query @ Wqr^T + b
__device__ float g_Wf[DD * DD];             // mlp2 @ mlp1, natural [n][k]
__device__ float g_bf[DD];                  // mlp2 @ b1 + b2
__device__ float g_WsHi[DD * DD];           // tf32 hi/lo splits, natural [n][k]
__device__ float g_WsLo[DD * DD];
__device__ float g_WfHi[DD * DD];
__device__ float g_WfLo[DD * DD];

__device__ __forceinline__ uint32_t f2tf32(float x) {
    uint32_t r;
    asm("cvt.rna.tf32.f32 %0, %1;" : "=r"(r) : "f"(x));
    return r;
}

// m16n8k8 tf32 MMA (baseline PTX, compute_80+; legacy tensor-core path)
__device__ __forceinline__ void mma1688(float* d, const uint32_t* a, const uint32_t* b) {
    asm volatile(
        "mma.sync.aligned.m16n8k8.row.col.f32.tf32.tf32.f32 "
        "{%0,%1,%2,%3}, {%4,%5,%6,%7}, {%8,%9}, {%0,%1,%2,%3};"
        : "+f"(d[0]), "+f"(d[1]), "+f"(d[2]), "+f"(d[3])
        : "r"(a[0]), "r"(a[1]), "r"(a[2]), "r"(a[3]), "r"(b[0]), "r"(b[1]));
}

// ================= prep: Wf (natural [n][k]), bf, Rr, Qq =================
__global__ void prep_kernel(const float* __restrict__ mlp1_w, const float* __restrict__ mlp1_b,
                            const float* __restrict__ mlp2_w, const float* __restrict__ mlp2_b,
                            const float* __restrict__ rela,   const float* __restrict__ Wr,
                            const float* __restrict__ query,  const float* __restrict__ Wqr,
                            const float* __restrict__ Wqr_b,  int R)
{
    int t = threadIdx.x;
    int bx = blockIdx.x;
    if (bx < DD) {
        int i = bx;
        float acc = 0.f;
        for (int j = 0; j < DD; j++) acc += mlp2_w[i * DD + j] * mlp1_w[j * DD + t];
        g_Wf[i * DD + t] = acc;
        __shared__ float s[DD];
        s[t] = mlp2_w[i * DD + t] * mlp1_b[t];
        __syncthreads();
        if (t == 0) {
            float b = 0.f;
            for (int j = 0; j < DD; j++) b += s[j];
            g_bf[i] = b + mlp2_b[i];
        }
    } else if (bx < DD + R) {
        int r = bx - DD;
        float acc = 0.f;
        for (int d = 0; d < DD; d++) acc += rela[r * DD + d] * Wr[t * DD + d];
        g_Rr[r * DD + t] = acc;
    } else {
        int b = bx - DD - R;
        float acc = Wqr_b[t];
        for (int d = 0; d < DD; d++) acc += query[b * DD + d] * Wqr[t * DD + d];
        g_Qq[b * DD + t] = acc;
    }
}

// split Ws and Wf into tf32 hi/lo (values stored as fp32 with zeroed low mantissa)
__global__ void split_kernel(const float* __restrict__ Ws) {
    int i = blockIdx.x * 256 + threadIdx.x;
    if (i >= DD * DD) return;
    float w1 = Ws[i];
    float h1 = __uint_as_float(f2tf32(w1));
    g_WsHi[i] = h1;
    g_WsLo[i] = __uint_as_float(f2tf32(w1 - h1));
    float w2 = g_Wf[i];
    float h2 = __uint_as_float(f2tf32(w2));
    g_WfHi[i] = h2;
    g_WfLo[i] = __uint_as_float(f2tf32(w2 - h2));
}

// ================= tensor GEMM: C[M,128] = epi(A @ W^T), W natural [n][k] =================
// CTA: 256 threads (8 warps), tile 64m x 64n (N split over 2 CTAs).
// Warp grid 2m x 4n; warp tile 32m x 16n = 2x2 of m16n8k8, 16 k-steps.
// tf32x3 split: D = ah*wh + ah*wl + al*wh. W hi/lo pre-split; A split in regs.
#define STR 132                              // padded smem row stride (floats)
#define SWH_OFF (64 * STR)
#define SWL_OFF (128 * STR)
#define SM_BYTES (192 * STR * 4)             // 101,376 B -> 2 CTAs/SM

__global__ __launch_bounds__(256, 2)
void mma_gemm(const float* __restrict__ A, const float* __restrict__ Whi,
              const float* __restrict__ Wlo, const float* __restrict__ bias,
              const int* __restrict__ deg, float* __restrict__ C, int M, int mode)
{
    extern __shared__ float smem[];
    float* sA  = smem;
    float* sWh = smem + SWH_OFF;
    float* sWl = smem + SWL_OFF;

    const int tid = threadIdx.x;
    const int mb = blockIdx.x >> 1;
    const int nb = blockIdx.x & 1;
    const int m0 = mb * 64;
    const int n0 = nb * 64;

    // ---- fill smem: A tile (64 x 128), W hi/lo halves (64n x 128k) ----
    const float4* A4 = reinterpret_cast<const float4*>(A);
    const float4* WH4 = reinterpret_cast<const float4*>(Whi);
    const float4* WL4 = reinterpret_cast<const float4*>(Wlo);
    #pragma unroll
    for (int i = tid; i < 64 * 32; i += 256) {
        int row = i >> 5, c4 = i & 31;
        int gr = m0 + row;
        float4 v = make_float4(0.f, 0.f, 0.f, 0.f);
        if (gr < M) v = A4[(size_t)gr * 32 + c4];
        *reinterpret_cast<float4*>(sA + row * STR + c4 * 4) = v;
        int wrow = n0 + row;
        *reinterpret_cast<float4*>(sWh + row * STR + c4 * 4) = WH4[(size_t)wrow * 32 + c4];
        *reinterpret_cast<float4*>(sWl + row * STR + c4 * 4) = WL4[(size_t)wrow * 32 + c4];
    }
    __syncthreads();

    const int lane = tid & 31;
    const int wid = tid >> 5;
    const int g = lane >> 2;           // group id 0..7
    const int t4 = lane & 3;           // thread-in-group 0..3
    const int wm = (wid >> 2) * 32;    // warp m offset: 0 | 32
    const int wn = (wid & 3) * 16;     // warp n offset: 0,16,32,48

    const float* aB  = sA  + (wm + g) * STR;
    const float* bhB = sWh + (wn + g) * STR;
    const float* blB = sWl + (wn + g) * STR;

    float acc[2][2][4];
    #pragma unroll
    for (int mt = 0; mt < 2; mt++)
        #pragma unroll
        for (int nt = 0; nt < 2; nt++)
            #pragma unroll
            for (int q = 0; q < 4; q++) acc[mt][nt][q] = 0.f;

    #pragma unroll 4
    for (int ks = 0; ks < 16; ks++) {
        const int k0 = ks * 8;
        // A fragments (2 m-tiles), split hi/lo in regs
        uint32_t ah[2][4], al[2][4];
        #pragma unroll
        for (int mt = 0; mt < 2; mt++) {
            const float* b = aB + mt * 16 * STR;
            float f[4];
            f[0] = b[k0 + t4];
            f[1] = b[8 * STR + k0 + t4];
            f[2] = b[k0 + t4 + 4];
            f[3] = b[8 * STR + k0 + t4 + 4];
            #pragma unroll
            for (int q = 0; q < 4; q++) {
                uint32_t h = f2tf32(f[q]);
                ah[mt][q] = h;
                al[mt][q] = f2tf32(f[q] - __uint_as_float(h));
            }
        }
        // B fragments (2 n-tiles) hi/lo: bits already tf32-valued
        #pragma unroll
        for (int nt = 0; nt < 2; nt++) {
            const float* bh = bhB + nt * 8 * STR;
            const float* bl = blB + nt * 8 * STR;
            uint32_t bhf[2], blf[2];
            bhf[0] = __float_as_uint(bh[k0 + t4]);
            bhf[1] = __float_as_uint(bh[k0 + t4 + 4]);
            blf[0] = __float_as_uint(bl[k0 + t4]);
            blf[1] = __float_as_uint(bl[k0 + t4 + 4]);
            #pragma unroll
            for (int mt = 0; mt < 2; mt++) {
                mma1688(acc[mt][nt], ah[mt], bhf);
                mma1688(acc[mt][nt], al[mt], bhf);
                mma1688(acc[mt][nt], ah[mt], blf);
            }
        }
    }

    // ---- epilogue: direct global stores (float2 pairs) ----
    #pragma unroll
    for (int mt = 0; mt < 2; mt++) {
        int r0 = m0 + wm + mt * 16 + g;
        int r1 = r0 + 8;
        bool k0ok = r0 < M, k1ok = r1 < M;
        bool keep0 = true, keep1 = true;
        if (mode == 1) {
            keep0 = k0ok && deg[r0] > 0;
            keep1 = k1ok && deg[r1] > 0;
        }
        #pragma unroll
        for (int nt = 0; nt < 2; nt++) {
            int col = n0 + wn + nt * 8 + 2 * t4;
            float c0 = acc[mt][nt][0], c1 = acc[mt][nt][1];
            float c2 = acc[mt][nt][2], c3 = acc[mt][nt][3];
            if (mode == 1) {
                float b0 = bias[col], b1 = bias[col + 1];
                c0 = keep0 ? fmaxf(c0 + b0, 0.f) : 0.f;
                c1 = keep0 ? fmaxf(c1 + b1, 0.f) : 0.f;
                c2 = keep1 ? fmaxf(c2 + b0, 0.f) : 0.f;
                c3 = keep1 ? fmaxf(c3 + b1, 0.f) : 0.f;
            }
            if (k0ok) *reinterpret_cast<float2*>(C + (size_t)r0 * DD + col) = make_float2(c0, c1);
            if (k1ok) *reinterpret_cast<float2*>(C + (size_t)r1 * DD + col) = make_float2(c2, c3);
        }
    }
}

// ================= edge kernel (unchanged) =================
__global__ __launch_bounds__(256)
void edge_kernel(const int4* __restrict__ edges, const float* __restrict__ Wattn,
                 const float* __restrict__ hidden, const float* __restrict__ rela, int E)
{
    int e = blockIdx.x * 8 + (threadIdx.x >> 5);
    if (e >= E) return;
    int lane = threadIdx.x & 31;
    int4 ed = edges[e];            // x=bat, y=sub(flat), z=rel, w=obj(flat)
    int c = lane * 4;

    float4 hs = *reinterpret_cast<const float4*>(g_Hs + (size_t)ed.y * DD + c);
    float4 rr = *reinterpret_cast<const float4*>(g_Rr + (size_t)ed.z * DD + c);
    float4 qq = *reinterpret_cast<const float4*>(g_Qq + (size_t)ed.x * DD + c);
    float4 wa = *reinterpret_cast<const float4*>(Wattn + c);

    float hx = fmaxf(hs.x + rr.x + qq.x, 0.f);
    float hy = fmaxf(hs.y + rr.y + qq.y, 0.f);
    float hz = fmaxf(hs.z + rr.z + qq.z, 0.f);
    float hw = fmaxf(hs.w + rr.w + qq.w, 0.f);
    float p = hx * wa.x + hy * wa.y + hz * wa.z + hw * wa.w;
    #pragma unroll
    for (int o = 16; o > 0; o >>= 1) p += __shfl_xor_sync(0xffffffffu, p, o);
    float alpha = 1.f / (1.f + __expf(-p));

    float4 mh = *reinterpret_cast<const float4*>(hidden + (size_t)ed.y * DD + c);
    float4 mr = *reinterpret_cast<const float4*>(rela + (size_t)ed.z * DD + c);
    float mx = mh.x * mr.x * alpha;
    float my = mh.y * mr.y * alpha;
    float mz = mh.z * mr.z * alpha;
    float mw = mh.w * mr.w * alpha;

    float* dst = g_agg + (size_t)ed.w * DD + c;
    asm volatile("red.global.add.v4.f32 [%0], {%1,%2,%3,%4};"
                 :: "l"(dst), "f"(mx), "f"(my), "f"(mz), "f"(mw) : "memory");
    if (lane == 0) atomicAdd(&g_deg[ed.w], 1);
}

// ================= launch =================
extern "C" void kernel_launch(void* const* d_in, const int* in_sizes, int n_in,
                              void* d_out, int out_size)
{
    const float* query  = (const float*)d_in[0];
    const float* hidden = (const float*)d_in[3];
    const int*   edges  = (const int*)d_in[4];
    const float* Ws     = (const float*)d_in[6];
    const float* Wr     = (const float*)d_in[7];
    const float* Wqr    = (const float*)d_in[8];
    const float* Wqr_b  = (const float*)d_in[9];
    const float* Wattn  = (const float*)d_in[10];
    const float* rela   = (const float*)d_in[11];
    const float* mlp1_w = (const float*)d_in[12];
    const float* mlp1_b = (const float*)d_in[13];
    const float* mlp2_w = (const float*)d_in[14];
    const float* mlp2_b = (const float*)d_in[15];

    int M = in_sizes[3] / DD;     // B*N = 200000
    int E = in_sizes[4] / 4;      // 600000
    int R = in_sizes[11] / DD;    // 200
    int B = in_sizes[0] / DD;     // 4

    void *aggp = 0, *degp = 0, *hsp = 0, *bfp = 0;
    void *wshi = 0, *wslo = 0, *wfhi = 0, *wflo = 0;
    cudaGetSymbolAddress(&aggp, g_agg);
    cudaGetSymbolAddress(&degp, g_deg);
    cudaGetSymbolAddress(&hsp,  g_Hs);
    cudaGetSymbolAddress(&bfp,  g_bf);
    cudaGetSymbolAddress(&wshi, g_WsHi);
    cudaGetSymbolAddress(&wslo, g_WsLo);
    cudaGetSymbolAddress(&wfhi, g_WfHi);
    cudaGetSymbolAddress(&wflo, g_WfLo);

    cudaMemsetAsync(aggp, 0, (size_t)M * DD * sizeof(float), 0);
    cudaMemsetAsync(degp, 0, (size_t)M * sizeof(int), 0);

    prep_kernel<<<DD + R + B, DD>>>(mlp1_w, mlp1_b, mlp2_w, mlp2_b,
                                    rela, Wr, query, Wqr, Wqr_b, R);
    split_kernel<<<(DD * DD + 255) / 256, 256>>>(Ws);

    cudaFuncSetAttribute(mma_gemm, cudaFuncAttributeMaxDynamicSharedMemorySize, SM_BYTES);
    int grid = ((M + 63) / 64) * 2;    // x2 for the two N-halves

    // Hs = hidden @ Ws^T
    mma_gemm<<<grid, 256, SM_BYTES>>>(hidden, (const float*)wshi, (const float*)wslo,
                                      nullptr, nullptr, (float*)hsp, M, 0);
    // per-edge attention + scatter
    edge_kernel<<<(E + 7) / 8, 256>>>((const int4*)edges, Wattn, hidden, rela, E);

    // out = mask(deg>0) * relu(agg @ Wf^T + bf)
    mma_gemm<<<grid, 256, SM_BYTES>>>((const float*)aggp, (const float*)wfhi, (const float*)wflo,
                                      (const float*)bfp, (const int*)degp,
                                      (float*)d_out, M, 1);
}

// round 9
// speedup vs baseline: 1.1645x; 1.1645x over previous
#include <cuda_runtime.h>
#include <cstdint>

#define DD 128
#define MAXM 200000
#define MAXR 256
#define MAXB 8

// -------- scratch (static device memory; no allocs allowed) --------
__device__ float g_Hs[(size_t)MAXM * DD];   // hidden @ Ws^T      (102.4 MB)
__device__ float g_agg[(size_t)MAXM * DD];  // segment_sum output (102.4 MB)
__device__ int   g_deg[MAXM];
__device__ float g_Rr[MAXR * DD];           // rela_embed @ Wr^T
__device__ float g_Qq[MAXB * DD];           // query @ Wqr^T + b
__device__ float g_Wf[DD * DD];             // (mlp2 @ mlp1)^T   -- stored [k][n]
__device__ float g_bf[DD];                  // mlp2 @ b1 + b2
__device__ float g_WsT[DD * DD];            // Ws_attn_w^T       -- stored [k][n]

// -------- packed f32x2 helpers (sm_103a FFMA2 pipe: 2 FMA / instr) --------
__device__ __forceinline__ unsigned long long pack2(float lo, float hi) {
    unsigned long long r;
    asm("mov.b64 %0, {%1,%2};" : "=l"(r) : "f"(lo), "f"(hi));
    return r;
}
__device__ __forceinline__ void fma2(unsigned long long& acc, unsigned long long a, unsigned long long b) {
    asm("fma.rn.f32x2 %0, %1, %2, %0;" : "+l"(acc) : "l"(a), "l"(b));
}
__device__ __forceinline__ float2 unpack2(unsigned long long v) {
    float lo, hi;
    asm("mov.b64 {%0,%1}, %2;" : "=f"(lo), "=f"(hi) : "l"(v));
    return make_float2(lo, hi);
}

// -------- tiny precompute: WfT, bf, Rr, Qq, WsT --------
__global__ void prep_kernel(const float* __restrict__ mlp1_w, const float* __restrict__ mlp1_b,
                            const float* __restrict__ mlp2_w, const float* __restrict__ mlp2_b,
                            const float* __restrict__ rela,   const float* __restrict__ Wr,
                            const float* __restrict__ query,  const float* __restrict__ Wqr,
                            const float* __restrict__ Wqr_b,  const float* __restrict__ Ws,
                            int R, int B)
{
    int t = threadIdx.x;
    int bx = blockIdx.x;
    if (bx < DD) {
        int i = bx;                           // output dim (n) of fused weight
        float acc = 0.f;
        for (int j = 0; j < DD; j++) acc += mlp2_w[i * DD + j] * mlp1_w[j * DD + t];
        g_Wf[t * DD + i] = acc;               // store TRANSPOSED: [k][n]
        __shared__ float s[DD];
        s[t] = mlp2_w[i * DD + t] * mlp1_b[t];
        __syncthreads();
        if (t == 0) {
            float b = 0.f;
            for (int j = 0; j < DD; j++) b += s[j];
            g_bf[i] = b + mlp2_b[i];
        }
    } else if (bx < 2 * DD) {
        int n = bx - DD;                      // transpose Ws: g_WsT[k][n] = Ws[n][k]
        g_WsT[t * DD + n] = Ws[n * DD + t];
    } else if (bx < 2 * DD + R) {
        int r = bx - 2 * DD;                  // Rr[r][t] = rela[r]·Wr[t]
        float acc = 0.f;
        for (int d = 0; d < DD; d++) acc += rela[r * DD + d] * Wr[t * DD + d];
        g_Rr[r * DD + t] = acc;
    } else {
        int b = bx - 2 * DD - R;              // Qq[b][t] = query[b]·Wqr[t] + b[t]
        float acc = Wqr_b[t];
        for (int d = 0; d < DD; d++) acc += query[b * DD + d] * Wqr[t * DD + d];
        g_Qq[b * DD + t] = acc;
    }
}

// -------- GEMM (R6 config): C[M,128] = epi(A[M,128] @ WT[128,128]) --------
// WT pre-transposed [k][n]. Tile BM=128 x BN=64, 256 threads, thread tile 8x4.
// smem 96KB -> 2 CTAs/SM. mode 1: relu(x + bias[n]), zeroed where deg[row]==0.
__global__ __launch_bounds__(256, 2)
void gemm128_kernel(const float* __restrict__ A, const float* __restrict__ WT,
                    const float* __restrict__ bias, const int* __restrict__ deg,
                    float* __restrict__ C, int M, int mode)
{
    extern __shared__ float smem[];
    float* sA = smem;               // 128(m) x 128(k)
    float* sW = smem + DD * DD;     // 128(k) x 64(n half)

    const int tid = threadIdx.x;
    const int mb = blockIdx.x >> 1;
    const int nb = blockIdx.x & 1;
    const int m0 = mb * 128;
    const int n0 = nb * 64;

    const float4* A4 = reinterpret_cast<const float4*>(A);
    float4* sA4 = reinterpret_cast<float4*>(sA);
    #pragma unroll
    for (int i = tid; i < DD * DD / 4; i += 256) {
        int row = i >> 5;
        int gr = m0 + row;
        float4 v = make_float4(0.f, 0.f, 0.f, 0.f);
        if (gr < M) v = A4[(size_t)gr * 32 + (i & 31)];
        sA4[i] = v;
    }
    const float4* W4 = reinterpret_cast<const float4*>(WT);
    float4* sW4 = reinterpret_cast<float4*>(sW);
    #pragma unroll
    for (int i = tid; i < DD * 64 / 4; i += 256) {
        int row = i >> 4;
        sW4[i] = W4[row * 32 + nb * 16 + (i & 15)];
    }
    __syncthreads();

    const int tx = tid & 15;        // col group: 4 cols (n) at n0 + tx*4
    const int ty = tid >> 4;        // row group: 8 rows (m) at ty*8
    const float* sAr = sA + ty * 8 * DD;
    const float* sWc = sW + tx * 4;

    unsigned long long acc[8][2];
    #pragma unroll
    for (int i = 0; i < 8; i++) { acc[i][0] = 0ULL; acc[i][1] = 0ULL; }

    #pragma unroll 2
    for (int k = 0; k < DD; k += 4) {
        float4 a4[8];
        #pragma unroll
        for (int i = 0; i < 8; i++)
            a4[i] = *reinterpret_cast<const float4*>(sAr + i * DD + k);
        ulonglong2 w[4];
        #pragma unroll
        for (int kk = 0; kk < 4; kk++)
            w[kk] = *reinterpret_cast<const ulonglong2*>(sWc + (size_t)(k + kk) * 64);
        #pragma unroll
        for (int kk = 0; kk < 4; kk++) {
            #pragma unroll
            for (int i = 0; i < 8; i++) {
                float a = (&a4[i].x)[kk];
                unsigned long long ad = pack2(a, a);
                fma2(acc[i][0], ad, w[kk].x);
                fma2(acc[i][1], ad, w[kk].y);
            }
        }
    }

    #pragma unroll
    for (int i = 0; i < 8; i++) {
        int row = m0 + ty * 8 + i;
        if (row >= M) continue;
        float out[4];
        float2 v0 = unpack2(acc[i][0]);
        float2 v1 = unpack2(acc[i][1]);
        out[0] = v0.x; out[1] = v0.y; out[2] = v1.x; out[3] = v1.y;
        if (mode == 1) {
            bool keep = deg[row] > 0;
            #pragma unroll
            for (int j = 0; j < 4; j++) {
                float x = fmaxf(out[j] + bias[n0 + tx * 4 + j], 0.f);
                out[j] = keep ? x : 0.f;
            }
        }
        *reinterpret_cast<float4*>(C + (size_t)row * DD + n0 + tx * 4) =
            make_float4(out[0], out[1], out[2], out[3]);
    }
}

// -------- edge kernel: TWO edges per warp (MLP: 10 outstanding gathers) --------
// alpha = sigmoid( W_attn · relu(Hs[sub] + Rr[rel] + Qq[bat]) )
// agg[obj] += hidden[sub] * rela[rel] * alpha   (vector red.global)
__global__ __launch_bounds__(256)
void edge_kernel(const int4* __restrict__ edges, const float* __restrict__ Wattn,
                 const float* __restrict__ hidden, const float* __restrict__ rela, int E)
{
    const int base = blockIdx.x * 16 + ((threadIdx.x >> 5) << 1);
    const int lane = threadIdx.x & 31;
    const int c = lane * 4;
    const bool v0 = base < E;
    const bool v1 = base + 1 < E;
    const int4 ed0 = v0 ? edges[base]     : make_int4(0, 0, 0, 0);
    const int4 ed1 = v1 ? edges[base + 1] : make_int4(0, 0, 0, 0);

    // ---- issue ALL gathers up front (maximize outstanding loads) ----
    float4 hs0 = *reinterpret_cast<const float4*>(g_Hs + (size_t)ed0.y * DD + c);
    float4 hs1 = *reinterpret_cast<const float4*>(g_Hs + (size_t)ed1.y * DD + c);
    float4 mh0 = *reinterpret_cast<const float4*>(hidden + (size_t)ed0.y * DD + c);
    float4 mh1 = *reinterpret_cast<const float4*>(hidden + (size_t)ed1.y * DD + c);
    float4 rr0 = *reinterpret_cast<const float4*>(g_Rr + (size_t)ed0.z * DD + c);
    float4 rr1 = *reinterpret_cast<const float4*>(g_Rr + (size_t)ed1.z * DD + c);
    float4 mr0 = *reinterpret_cast<const float4*>(rela + (size_t)ed0.z * DD + c);
    float4 mr1 = *reinterpret_cast<const float4*>(rela + (size_t)ed1.z * DD + c);
    float4 qq0 = *reinterpret_cast<const float4*>(g_Qq + (size_t)ed0.x * DD + c);
    float4 qq1 = *reinterpret_cast<const float4*>(g_Qq + (size_t)ed1.x * DD + c);
    float4 wa  = *reinterpret_cast<const float4*>(Wattn + c);

    // ---- attention logits (both edges; independent chains) ----
    float p0 = fmaxf(hs0.x + rr0.x + qq0.x, 0.f) * wa.x
             + fmaxf(hs0.y + rr0.y + qq0.y, 0.f) * wa.y
             + fmaxf(hs0.z + rr0.z + qq0.z, 0.f) * wa.z
             + fmaxf(hs0.w + rr0.w + qq0.w, 0.f) * wa.w;
    float p1 = fmaxf(hs1.x + rr1.x + qq1.x, 0.f) * wa.x
             + fmaxf(hs1.y + rr1.y + qq1.y, 0.f) * wa.y
             + fmaxf(hs1.z + rr1.z + qq1.z, 0.f) * wa.z
             + fmaxf(hs1.w + rr1.w + qq1.w, 0.f) * wa.w;
    #pragma unroll
    for (int o = 16; o > 0; o >>= 1) {
        p0 += __shfl_xor_sync(0xffffffffu, p0, o);
        p1 += __shfl_xor_sync(0xffffffffu, p1, o);
    }
    float alpha0 = 1.f / (1.f + __expf(-p0));
    float alpha1 = 1.f / (1.f + __expf(-p1));

    // ---- messages + scatter ----
    if (v0) {
        float* dst = g_agg + (size_t)ed0.w * DD + c;
        asm volatile("red.global.add.v4.f32 [%0], {%1,%2,%3,%4};"
                     :: "l"(dst),
                        "f"(mh0.x * mr0.x * alpha0), "f"(mh0.y * mr0.y * alpha0),
                        "f"(mh0.z * mr0.z * alpha0), "f"(mh0.w * mr0.w * alpha0) : "memory");
        if (lane == 0) atomicAdd(&g_deg[ed0.w], 1);
    }
    if (v1) {
        float* dst = g_agg + (size_t)ed1.w * DD + c;
        asm volatile("red.global.add.v4.f32 [%0], {%1,%2,%3,%4};"
                     :: "l"(dst),
                        "f"(mh1.x * mr1.x * alpha1), "f"(mh1.y * mr1.y * alpha1),
                        "f"(mh1.z * mr1.z * alpha1), "f"(mh1.w * mr1.w * alpha1) : "memory");
        if (lane == 0) atomicAdd(&g_deg[ed1.w], 1);
    }
}

// -------- launch --------
extern "C" void kernel_launch(void* const* d_in, const int* in_sizes, int n_in,
                              void* d_out, int out_size)
{
    const float* query  = (const float*)d_in[0];
    const float* hidden = (const float*)d_in[3];
    const int*   edges  = (const int*)d_in[4];
    const float* Ws     = (const float*)d_in[6];
    const float* Wr     = (const float*)d_in[7];
    const float* Wqr    = (const float*)d_in[8];
    const float* Wqr_b  = (const float*)d_in[9];
    const float* Wattn  = (const float*)d_in[10];
    const float* rela   = (const float*)d_in[11];
    const float* mlp1_w = (const float*)d_in[12];
    const float* mlp1_b = (const float*)d_in[13];
    const float* mlp2_w = (const float*)d_in[14];
    const float* mlp2_b = (const float*)d_in[15];

    int M = in_sizes[3] / DD;     // B*N = 200000
    int E = in_sizes[4] / 4;      // 600000
    int R = in_sizes[11] / DD;    // 200
    int B = in_sizes[0] / DD;     // 4

    void *aggp = 0, *degp = 0, *hsp = 0, *wfp = 0, *bfp = 0, *wstp = 0;
    cudaGetSymbolAddress(&aggp, g_agg);
    cudaGetSymbolAddress(&degp, g_deg);
    cudaGetSymbolAddress(&hsp,  g_Hs);
    cudaGetSymbolAddress(&wfp,  g_Wf);
    cudaGetSymbolAddress(&bfp,  g_bf);
    cudaGetSymbolAddress(&wstp, g_WsT);

    cudaMemsetAsync(aggp, 0, (size_t)M * DD * sizeof(float), 0);
    cudaMemsetAsync(degp, 0, (size_t)M * sizeof(int), 0);

    prep_kernel<<<2 * DD + R + B, DD>>>(mlp1_w, mlp1_b, mlp2_w, mlp2_b,
                                        rela, Wr, query, Wqr, Wqr_b, Ws, R, B);

    size_t smem = (size_t)(DD * DD + DD * 64) * sizeof(float);   // 96 KB
    cudaFuncSetAttribute(gemm128_kernel, cudaFuncAttributeMaxDynamicSharedMemorySize, (int)smem);

    int grid = ((M + 127) / 128) * 2;    // x2 for the two N-halves

    // Hs = hidden @ Ws^T
    gemm128_kernel<<<grid, 256, smem>>>(hidden, (const float*)wstp, nullptr, nullptr,
                                        (float*)hsp, M, 0);
    // per-edge attention + scatter (2 edges per warp, 16 per block)
    edge_kernel<<<(E + 15) / 16, 256>>>((const int4*)edges, Wattn, hidden, rela, E);

    // out = mask(deg>0) * relu(agg @ (mlp2·mlp1)^T + b')
    gemm128_kernel<<<grid, 256, smem>>>((const float*)aggp, (const float*)wfp,
                                        (const float*)bfp, (const int*)degp,
                                        (float*)d_out, M, 1);
}